// round 2
// baseline (speedup 1.0000x reference)
#include <cuda_runtime.h>
#include <cuda_bf16.h>
#include <cstdint>

// Problem constants
#define BB 4
#define TT 2048
#define CC 1024
#define HH 16
#define DD 64
#define SHARED_D 16
#define PRIV_D 48
#define MM (BB * TT)          // 8192 token rows
#define BH (BB * HH)          // 64 batch-heads

// ---------------------------------------------------------------------------
// Scratch (device globals; no allocation allowed)
// ---------------------------------------------------------------------------
__device__ float g_share[MM * SHARED_D];       // 0.5 MB
__device__ float g_qp[MM * (HH * PRIV_D)];     // 25 MB
__device__ float g_kp[MM * (HH * PRIV_D)];     // 25 MB
__device__ float g_vf[MM * CC];                // 33.5 MB
__device__ float g_q[BH * TT * DD];            // 33.5 MB
__device__ float g_k[BH * TT * DD];            // 33.5 MB
__device__ float g_v[BH * TT * DD];            // 33.5 MB
__device__ float g_y[MM * CC];                 // 33.5 MB

// ---------------------------------------------------------------------------
// Generic tiled fp32 GEMM:  C[M,N] = A[M,K] @ W[K,N] + bias[N]
// 64x64 tile, TK=16, 256 threads, 4x4 micro-tile per thread.
// Requires K % 16 == 0, M % 64 == 0 (true here: K=1024, M=8192).
// ---------------------------------------------------------------------------
__global__ void gemm_bias_kernel(const float* __restrict__ A,
                                 const float* __restrict__ W,
                                 const float* __restrict__ bias,
                                 float* __restrict__ C,
                                 int M, int N, int K)
{
    const int TM = 64, TN = 64, TK = 16;
    __shared__ float As[TK][TM];   // k-major
    __shared__ float Ws[TK][TN];   // k-major

    int tid = threadIdx.x;
    int tx = tid & 15;
    int ty = tid >> 4;
    int m0 = blockIdx.y * TM;
    int n0 = blockIdx.x * TN;

    float acc[4][4] = {};

    for (int k0 = 0; k0 < K; k0 += TK) {
        // Load A tile: 64 x 16 = 1024 elems
        #pragma unroll
        for (int l = 0; l < 4; l++) {
            int idx = tid + l * 256;
            int mi = idx >> 4;        // 0..63
            int ki = idx & 15;        // 0..15
            As[ki][mi] = A[(size_t)(m0 + mi) * K + (k0 + ki)];
        }
        // Load W tile: 16 x 64 = 1024 elems (coalesced on N)
        #pragma unroll
        for (int l = 0; l < 4; l++) {
            int idx = tid + l * 256;
            int ki = idx >> 6;        // 0..15
            int ni = idx & 63;        // 0..63
            int gn = n0 + ni;
            Ws[ki][ni] = (gn < N) ? W[(size_t)(k0 + ki) * N + gn] : 0.f;
        }
        __syncthreads();

        #pragma unroll
        for (int kk = 0; kk < TK; kk++) {
            float4 a4 = *reinterpret_cast<const float4*>(&As[kk][ty * 4]);
            float4 w4 = *reinterpret_cast<const float4*>(&Ws[kk][tx * 4]);
            float a[4] = {a4.x, a4.y, a4.z, a4.w};
            float w[4] = {w4.x, w4.y, w4.z, w4.w};
            #pragma unroll
            for (int i = 0; i < 4; i++)
                #pragma unroll
                for (int j = 0; j < 4; j++)
                    acc[i][j] = fmaf(a[i], w[j], acc[i][j]);
        }
        __syncthreads();
    }

    #pragma unroll
    for (int i = 0; i < 4; i++) {
        int gm = m0 + ty * 4 + i;
        #pragma unroll
        for (int j = 0; j < 4; j++) {
            int gn = n0 + tx * 4 + j;
            if (gn < N)
                C[(size_t)gm * N + gn] = acc[i][j] + bias[gn];
        }
    }
}

// ---------------------------------------------------------------------------
// Assemble q/k/v into (B*H, T, 64) layout.
// q[bh,t,d] = d<16 ? share[b,t,d] : qp[b,t, h*48 + d-16]   (same for k)
// v[bh,t,d] = vf[b,t, h*64+d]
// idx bit layout: d(6) | t(11) | h(4) | b(2)
// ---------------------------------------------------------------------------
__global__ void assemble_qkv_kernel()
{
    int idx = blockIdx.x * blockDim.x + threadIdx.x;   // 0 .. 8388607
    int d = idx & 63;
    int t = (idx >> 6) & (TT - 1);
    int h = (idx >> 17) & (HH - 1);
    int b = idx >> 21;
    size_t row = (size_t)b * TT + t;

    float qv, kv;
    if (d < SHARED_D) {
        float s = g_share[row * SHARED_D + d];
        qv = s; kv = s;
    } else {
        size_t p = row * (HH * PRIV_D) + h * PRIV_D + (d - SHARED_D);
        qv = g_qp[p];
        kv = g_kp[p];
    }
    g_q[idx] = qv;
    g_k[idx] = kv;
    g_v[idx] = g_vf[row * CC + h * DD + d];
}

// ---------------------------------------------------------------------------
// Flash attention, causal, fp32. BM=BN=64, D=64.
// grid = (T/64, B*H), block = 256 (16x16), 64 KB dynamic smem.
// ---------------------------------------------------------------------------
__global__ void flash_attn_kernel(float* __restrict__ y)
{
    extern __shared__ float smem[];
    float* Qs = smem;               // [64][64] d-major: Qs[d*64 + i]
    float* Ks = smem + 4096;        // [64][64] d-major: Ks[d*64 + j]
    float* Vs = smem + 8192;        // [64][64] j-major: Vs[j*64 + d]
    float* Ps = smem + 12288;       // [64][64] Ps[i*64 + j]

    int mb = blockIdx.x;
    int bh = blockIdx.y;
    int tid = threadIdx.x;
    int tx = tid & 15;
    int ty = tid >> 4;
    const size_t base = (size_t)bh * TT * DD;
    const float scale = 0.125f;   // 1/sqrt(64)

    // Load Q tile (transposed to d-major)
    #pragma unroll
    for (int l = 0; l < 16; l++) {
        int idx = tid + l * 256;
        int i = idx >> 6, d = idx & 63;
        Qs[d * 64 + i] = g_q[base + (size_t)(mb * 64 + i) * DD + d];
    }

    float m_i[4], l_i[4], O[4][4];
    #pragma unroll
    for (int i = 0; i < 4; i++) {
        m_i[i] = -1e30f; l_i[i] = 0.f;
        #pragma unroll
        for (int c = 0; c < 4; c++) O[i][c] = 0.f;
    }

    for (int jb = 0; jb <= mb; jb++) {
        // Load K (transposed) and V (row-major) tiles
        #pragma unroll
        for (int l = 0; l < 16; l++) {
            int idx = tid + l * 256;
            int j = idx >> 6, d = idx & 63;
            size_t g = base + (size_t)(jb * 64 + j) * DD + d;
            Ks[d * 64 + j] = g_k[g];
            Vs[idx]        = g_v[g];
        }
        __syncthreads();

        // S = Q @ K^T
        float acc[4][4] = {};
        #pragma unroll
        for (int d = 0; d < 64; d++) {
            float4 a4 = *reinterpret_cast<const float4*>(&Qs[d * 64 + ty * 4]);
            float4 b4 = *reinterpret_cast<const float4*>(&Ks[d * 64 + tx * 4]);
            float a[4] = {a4.x, a4.y, a4.z, a4.w};
            float b2[4] = {b4.x, b4.y, b4.z, b4.w};
            #pragma unroll
            for (int i = 0; i < 4; i++)
                #pragma unroll
                for (int j = 0; j < 4; j++)
                    acc[i][j] = fmaf(a[i], b2[j], acc[i][j]);
        }

        // scale + causal mask (only on the diagonal block)
        if (jb == mb) {
            #pragma unroll
            for (int i = 0; i < 4; i++) {
                int gi = ty * 4 + i;
                #pragma unroll
                for (int j = 0; j < 4; j++) {
                    int gj = tx * 4 + j;
                    acc[i][j] = (gj <= gi) ? acc[i][j] * scale : -1e30f;
                }
            }
        } else {
            #pragma unroll
            for (int i = 0; i < 4; i++)
                #pragma unroll
                for (int j = 0; j < 4; j++)
                    acc[i][j] *= scale;
        }

        // row max across the 16 tx-threads (16-lane shuffle groups)
        float pm[4];
        #pragma unroll
        for (int i = 0; i < 4; i++) {
            pm[i] = fmaxf(fmaxf(acc[i][0], acc[i][1]), fmaxf(acc[i][2], acc[i][3]));
        }
        #pragma unroll
        for (int off = 1; off < 16; off <<= 1) {
            #pragma unroll
            for (int i = 0; i < 4; i++)
                pm[i] = fmaxf(pm[i], __shfl_xor_sync(0xffffffff, pm[i], off));
        }

        float alpha[4], ps[4];
        #pragma unroll
        for (int i = 0; i < 4; i++) {
            float mnew = fmaxf(m_i[i], pm[i]);
            alpha[i] = __expf(m_i[i] - mnew);
            m_i[i] = mnew;
            ps[i] = 0.f;
            #pragma unroll
            for (int j = 0; j < 4; j++) {
                float p = __expf(acc[i][j] - mnew);
                Ps[(ty * 4 + i) * 64 + tx * 4 + j] = p;
                ps[i] += p;
            }
        }
        #pragma unroll
        for (int off = 1; off < 16; off <<= 1) {
            #pragma unroll
            for (int i = 0; i < 4; i++)
                ps[i] += __shfl_xor_sync(0xffffffff, ps[i], off);
        }
        #pragma unroll
        for (int i = 0; i < 4; i++) {
            l_i[i] = l_i[i] * alpha[i] + ps[i];
            #pragma unroll
            for (int c = 0; c < 4; c++) O[i][c] *= alpha[i];
        }
        __syncthreads();   // Ps written by all threads before use

        // O += P @ V
        #pragma unroll
        for (int jj = 0; jj < 64; jj++) {
            float4 v4 = *reinterpret_cast<const float4*>(&Vs[jj * 64 + tx * 4]);
            float vv[4] = {v4.x, v4.y, v4.z, v4.w};
            float a[4];
            #pragma unroll
            for (int i = 0; i < 4; i++) a[i] = Ps[(ty * 4 + i) * 64 + jj];
            #pragma unroll
            for (int i = 0; i < 4; i++)
                #pragma unroll
                for (int c = 0; c < 4; c++)
                    O[i][c] = fmaf(a[i], vv[c], O[i][c]);
        }
        __syncthreads();   // done with Ks/Vs/Ps before next load
    }

    // Write y[b, t, h*64 + d] (row-major [8192, 1024])
    int h = bh & (HH - 1);
    int b = bh >> 4;
    #pragma unroll
    for (int i = 0; i < 4; i++) {
        int row = mb * 64 + ty * 4 + i;
        float inv = 1.f / l_i[i];
        size_t off = ((size_t)b * TT + row) * CC + h * DD + tx * 4;
        #pragma unroll
        for (int c = 0; c < 4; c++)
            g_y[off + c] = O[i][c] * inv;
    }
    (void)y;
}

// ---------------------------------------------------------------------------
// Launch
// ---------------------------------------------------------------------------
extern "C" void kernel_launch(void* const* d_in, const int* in_sizes, int n_in,
                              void* d_out, int out_size)
{
    const float* x       = (const float*)d_in[0];
    const float* W_share = (const float*)d_in[1];
    const float* b_share = (const float*)d_in[2];
    const float* Wq      = (const float*)d_in[3];
    const float* bq      = (const float*)d_in[4];
    const float* Wk      = (const float*)d_in[5];
    const float* bk      = (const float*)d_in[6];
    const float* Wv      = (const float*)d_in[7];
    const float* bv      = (const float*)d_in[8];
    const float* Wo      = (const float*)d_in[9];
    const float* bo      = (const float*)d_in[10];
    float* out = (float*)d_out;

    float *p_share, *p_qp, *p_kp, *p_vf, *p_y;
    cudaGetSymbolAddress((void**)&p_share, g_share);
    cudaGetSymbolAddress((void**)&p_qp, g_qp);
    cudaGetSymbolAddress((void**)&p_kp, g_kp);
    cudaGetSymbolAddress((void**)&p_vf, g_vf);
    cudaGetSymbolAddress((void**)&p_y, g_y);

    dim3 blk(256);

    // Projections
    gemm_bias_kernel<<<dim3(1, MM / 64), blk>>>(x, W_share, b_share, p_share, MM, SHARED_D, CC);
    gemm_bias_kernel<<<dim3(12, MM / 64), blk>>>(x, Wq, bq, p_qp, MM, HH * PRIV_D, CC);
    gemm_bias_kernel<<<dim3(12, MM / 64), blk>>>(x, Wk, bk, p_kp, MM, HH * PRIV_D, CC);
    gemm_bias_kernel<<<dim3(16, MM / 64), blk>>>(x, Wv, bv, p_vf, MM, CC, CC);

    // Assemble q/k/v into (BH, T, 64)
    assemble_qkv_kernel<<<(BH * TT * DD) / 256, blk>>>();

    // Flash attention
    static bool attr_set = false;
    cudaFuncSetAttribute(flash_attn_kernel, cudaFuncAttributeMaxDynamicSharedMemorySize, 65536);
    flash_attn_kernel<<<dim3(TT / 64, BH), blk, 65536>>>(p_y);

    // Output projection
    gemm_bias_kernel<<<dim3(16, MM / 64), blk>>>(p_y, Wo, bo, out, MM, CC, CC);

    (void)in_sizes; (void)n_in; (void)out_size; (void)attr_set;
}

// round 5
// speedup vs baseline: 1.8181x; 1.8181x over previous
#include <cuda_runtime.h>
#include <cuda_bf16.h>
#include <cstdint>

// Problem constants
#define BB 4
#define TT 2048
#define CC 1024
#define HH 16
#define DD 64
#define SHARED_D 16
#define PRIV_D 48
#define MM (BB * TT)          // 8192 token rows
#define BH (BB * HH)          // 64 batch-heads
#define GK 1024               // inner K of all projections

// ---------------------------------------------------------------------------
// Scratch (device globals; no allocation allowed)
// ---------------------------------------------------------------------------
__device__ float g_share[MM * SHARED_D];
__device__ float g_qp[MM * (HH * PRIV_D)];
__device__ float g_kp[MM * (HH * PRIV_D)];
__device__ float g_vf[MM * CC];
__device__ float g_q[BH * TT * DD];
__device__ float g_k[BH * TT * DD];
__device__ float g_v[BH * TT * DD];
__device__ float g_y[MM * CC];
// Transposed weights, K-major [N, K]
__device__ float g_WqT[768 * 1024];
__device__ float g_WkT[768 * 1024];
__device__ float g_WvT[1024 * 1024];
__device__ float g_WoT[1024 * 1024];

// ---------------------------------------------------------------------------
// tf32 helpers (mma.sync path — portable PTX, no sm_103a-only features)
// ---------------------------------------------------------------------------
static __device__ __forceinline__ uint32_t f2tf32(float x) {
    uint32_t r;
    asm("cvt.rna.tf32.f32 %0, %1;" : "=r"(r) : "f"(x));
    return r;
}

#define MMA_TF32(d, a, b) \
    asm volatile("mma.sync.aligned.m16n8k8.row.col.f32.tf32.tf32.f32 " \
                 "{%0,%1,%2,%3}, {%4,%5,%6,%7}, {%8,%9}, {%0,%1,%2,%3};" \
                 : "+f"((d)[0]), "+f"((d)[1]), "+f"((d)[2]), "+f"((d)[3]) \
                 : "r"((a)[0]), "r"((a)[1]), "r"((a)[2]), "r"((a)[3]), \
                   "r"((b)[0]), "r"((b)[1]))

// ---------------------------------------------------------------------------
// Weight transpose: W [K,N] row-major -> Wt [N,K] row-major
// ---------------------------------------------------------------------------
__global__ void transpose_kernel(const float* __restrict__ W, float* __restrict__ Wt,
                                 int K, int N) {
    __shared__ float tile[32][33];
    int n0 = blockIdx.x * 32, k0 = blockIdx.y * 32;
    int tx = threadIdx.x, ty = threadIdx.y;
    #pragma unroll
    for (int i = 0; i < 4; i++)
        tile[ty + i * 8][tx] = W[(size_t)(k0 + ty + i * 8) * N + n0 + tx];
    __syncthreads();
    #pragma unroll
    for (int i = 0; i < 4; i++)
        Wt[(size_t)(n0 + ty + i * 8) * K + k0 + tx] = tile[tx][ty + i * 8];
}

// ---------------------------------------------------------------------------
// Tensor-core GEMM (mma.sync tf32): C[M,N] = A[M,1024] @ Bt[N,1024]^T + bias[N]
// CTA tile 128x128, 8 warps (2 x 4), warp tile 64x32, K chunks of 32.
// Register-staged double buffering; smem padded to stride 36 (conflict-free).
// ---------------------------------------------------------------------------
#define SMS 36  // smem row stride (floats)

__global__ __launch_bounds__(256) void gemm_tf32mma(const float* __restrict__ A,
                                                    const float* __restrict__ Bt,
                                                    const float* __restrict__ bias,
                                                    float* __restrict__ C, int N)
{
    __shared__ uint32_t As[128 * SMS];
    __shared__ uint32_t Bs[128 * SMS];

    const int tid = threadIdx.x;
    const int wid = tid >> 5, lane = tid & 31;
    const int wm = wid & 1, wn = wid >> 1;   // warp grid: 2 (m) x 4 (n)
    const int g = lane >> 2, t = lane & 3;   // groupID / threadID-in-group
    const int m0 = blockIdx.y * 128, n0 = blockIdx.x * 128;

    float acc[4][4][4] = {};
    float4 ra[4], rb[4];

    // Prologue: global-load chunk 0 into registers
    #pragma unroll
    for (int l = 0; l < 4; l++) {
        int idx = tid + l * 256;
        int row = idx >> 3, c4 = idx & 7;
        ra[l] = *(const float4*)(A  + (size_t)(m0 + row) * GK + c4 * 4);
        rb[l] = *(const float4*)(Bt + (size_t)(n0 + row) * GK + c4 * 4);
    }

    for (int kc = 0; kc < 32; kc++) {
        __syncthreads();  // previous chunk's mma reads finished
        // Store staged regs -> smem with tf32 rounding
        #pragma unroll
        for (int l = 0; l < 4; l++) {
            int idx = tid + l * 256;
            int row = idx >> 3, c4 = idx & 7;
            uint4 ua, ub;
            ua.x = f2tf32(ra[l].x); ua.y = f2tf32(ra[l].y);
            ua.z = f2tf32(ra[l].z); ua.w = f2tf32(ra[l].w);
            ub.x = f2tf32(rb[l].x); ub.y = f2tf32(rb[l].y);
            ub.z = f2tf32(rb[l].z); ub.w = f2tf32(rb[l].w);
            *(uint4*)&As[row * SMS + c4 * 4] = ua;
            *(uint4*)&Bs[row * SMS + c4 * 4] = ub;
        }
        __syncthreads();

        // Prefetch next chunk into registers (overlaps with mma below)
        if (kc + 1 < 32) {
            #pragma unroll
            for (int l = 0; l < 4; l++) {
                int idx = tid + l * 256;
                int row = idx >> 3, c4 = idx & 7;
                ra[l] = *(const float4*)(A  + (size_t)(m0 + row) * GK + (kc + 1) * 32 + c4 * 4);
                rb[l] = *(const float4*)(Bt + (size_t)(n0 + row) * GK + (kc + 1) * 32 + c4 * 4);
            }
        }

        // Compute: 4 k-steps of 8, 16 mmas each
        #pragma unroll
        for (int ks = 0; ks < 4; ks++) {
            uint32_t af[4][4], bf[4][2];
            #pragma unroll
            for (int mt = 0; mt < 4; mt++) {
                int r = wm * 64 + mt * 16 + g;
                int c = ks * 8 + t;
                af[mt][0] = As[r * SMS + c];
                af[mt][1] = As[(r + 8) * SMS + c];
                af[mt][2] = As[r * SMS + c + 4];
                af[mt][3] = As[(r + 8) * SMS + c + 4];
            }
            #pragma unroll
            for (int nt = 0; nt < 4; nt++) {
                int n = wn * 32 + nt * 8 + g;
                int c = ks * 8 + t;
                bf[nt][0] = Bs[n * SMS + c];
                bf[nt][1] = Bs[n * SMS + c + 4];
            }
            #pragma unroll
            for (int mt = 0; mt < 4; mt++)
                #pragma unroll
                for (int nt = 0; nt < 4; nt++)
                    MMA_TF32(acc[mt][nt], af[mt], bf[nt]);
        }
    }

    // Epilogue: c0/c1 at (row, 2t), c2/c3 at (row+8, 2t)
    #pragma unroll
    for (int mt = 0; mt < 4; mt++) {
        int r0 = m0 + wm * 64 + mt * 16 + g;
        #pragma unroll
        for (int nt = 0; nt < 4; nt++) {
            int cc = n0 + wn * 32 + nt * 8 + 2 * t;
            float2 bi = *(const float2*)(bias + cc);
            float2 o0 = { acc[mt][nt][0] + bi.x, acc[mt][nt][1] + bi.y };
            float2 o1 = { acc[mt][nt][2] + bi.x, acc[mt][nt][3] + bi.y };
            *(float2*)(C + (size_t)r0 * N + cc) = o0;
            *(float2*)(C + (size_t)(r0 + 8) * N + cc) = o1;
        }
    }
}

// ---------------------------------------------------------------------------
// SIMT GEMM (kept for the tiny N=16 shared projection)
// ---------------------------------------------------------------------------
__global__ void gemm_bias_kernel(const float* __restrict__ A,
                                 const float* __restrict__ W,
                                 const float* __restrict__ bias,
                                 float* __restrict__ C,
                                 int M, int N, int K)
{
    const int TM = 64, TN = 64, TK = 16;
    __shared__ float Asm[TK][TM];
    __shared__ float Wsm[TK][TN];

    int tid = threadIdx.x;
    int tx = tid & 15;
    int ty = tid >> 4;
    int m0 = blockIdx.y * TM;
    int n0 = blockIdx.x * TN;

    float acc[4][4] = {};

    for (int k0 = 0; k0 < K; k0 += TK) {
        #pragma unroll
        for (int l = 0; l < 4; l++) {
            int idx = tid + l * 256;
            int mi = idx >> 4;
            int ki = idx & 15;
            Asm[ki][mi] = A[(size_t)(m0 + mi) * K + (k0 + ki)];
        }
        #pragma unroll
        for (int l = 0; l < 4; l++) {
            int idx = tid + l * 256;
            int ki = idx >> 6;
            int ni = idx & 63;
            int gn = n0 + ni;
            Wsm[ki][ni] = (gn < N) ? W[(size_t)(k0 + ki) * N + gn] : 0.f;
        }
        __syncthreads();

        #pragma unroll
        for (int kk = 0; kk < TK; kk++) {
            float4 a4 = *reinterpret_cast<const float4*>(&Asm[kk][ty * 4]);
            float4 w4 = *reinterpret_cast<const float4*>(&Wsm[kk][tx * 4]);
            float a[4] = {a4.x, a4.y, a4.z, a4.w};
            float w[4] = {w4.x, w4.y, w4.z, w4.w};
            #pragma unroll
            for (int i = 0; i < 4; i++)
                #pragma unroll
                for (int j = 0; j < 4; j++)
                    acc[i][j] = fmaf(a[i], w[j], acc[i][j]);
        }
        __syncthreads();
    }

    #pragma unroll
    for (int i = 0; i < 4; i++) {
        int gm = m0 + ty * 4 + i;
        #pragma unroll
        for (int j = 0; j < 4; j++) {
            int gn = n0 + tx * 4 + j;
            if (gn < N)
                C[(size_t)gm * N + gn] = acc[i][j] + bias[gn];
        }
    }
}

// ---------------------------------------------------------------------------
// Assemble q/k/v into (B*H, T, 64) layout.
// ---------------------------------------------------------------------------
__global__ void assemble_qkv_kernel()
{
    int idx = blockIdx.x * blockDim.x + threadIdx.x;
    int d = idx & 63;
    int t = (idx >> 6) & (TT - 1);
    int h = (idx >> 17) & (HH - 1);
    int b = idx >> 21;
    size_t row = (size_t)b * TT + t;

    float qv, kv;
    if (d < SHARED_D) {
        float s = g_share[row * SHARED_D + d];
        qv = s; kv = s;
    } else {
        size_t p = row * (HH * PRIV_D) + h * PRIV_D + (d - SHARED_D);
        qv = g_qp[p];
        kv = g_kp[p];
    }
    g_q[idx] = qv;
    g_k[idx] = kv;
    g_v[idx] = g_vf[row * CC + h * DD + d];
}

// ---------------------------------------------------------------------------
// Flash attention, causal, fp32. BM=BN=64, D=64.
// ---------------------------------------------------------------------------
__global__ void flash_attn_kernel(float* __restrict__ y)
{
    extern __shared__ float smem[];
    float* Qs = smem;
    float* Ks = smem + 4096;
    float* Vs = smem + 8192;
    float* Ps = smem + 12288;

    int mb = blockIdx.x;
    int bh = blockIdx.y;
    int tid = threadIdx.x;
    int tx = tid & 15;
    int ty = tid >> 4;
    const size_t base = (size_t)bh * TT * DD;
    const float scale = 0.125f;

    #pragma unroll
    for (int l = 0; l < 16; l++) {
        int idx = tid + l * 256;
        int i = idx >> 6, d = idx & 63;
        Qs[d * 64 + i] = g_q[base + (size_t)(mb * 64 + i) * DD + d];
    }

    float m_i[4], l_i[4], O[4][4];
    #pragma unroll
    for (int i = 0; i < 4; i++) {
        m_i[i] = -1e30f; l_i[i] = 0.f;
        #pragma unroll
        for (int c = 0; c < 4; c++) O[i][c] = 0.f;
    }

    for (int jb = 0; jb <= mb; jb++) {
        #pragma unroll
        for (int l = 0; l < 16; l++) {
            int idx = tid + l * 256;
            int j = idx >> 6, d = idx & 63;
            size_t g = base + (size_t)(jb * 64 + j) * DD + d;
            Ks[d * 64 + j] = g_k[g];
            Vs[idx]        = g_v[g];
        }
        __syncthreads();

        float acc[4][4] = {};
        #pragma unroll
        for (int d = 0; d < 64; d++) {
            float4 a4 = *reinterpret_cast<const float4*>(&Qs[d * 64 + ty * 4]);
            float4 b4 = *reinterpret_cast<const float4*>(&Ks[d * 64 + tx * 4]);
            float a[4] = {a4.x, a4.y, a4.z, a4.w};
            float b2[4] = {b4.x, b4.y, b4.z, b4.w};
            #pragma unroll
            for (int i = 0; i < 4; i++)
                #pragma unroll
                for (int j = 0; j < 4; j++)
                    acc[i][j] = fmaf(a[i], b2[j], acc[i][j]);
        }

        if (jb == mb) {
            #pragma unroll
            for (int i = 0; i < 4; i++) {
                int gi = ty * 4 + i;
                #pragma unroll
                for (int j = 0; j < 4; j++) {
                    int gj = tx * 4 + j;
                    acc[i][j] = (gj <= gi) ? acc[i][j] * scale : -1e30f;
                }
            }
        } else {
            #pragma unroll
            for (int i = 0; i < 4; i++)
                #pragma unroll
                for (int j = 0; j < 4; j++)
                    acc[i][j] *= scale;
        }

        float pm[4];
        #pragma unroll
        for (int i = 0; i < 4; i++) {
            pm[i] = fmaxf(fmaxf(acc[i][0], acc[i][1]), fmaxf(acc[i][2], acc[i][3]));
        }
        #pragma unroll
        for (int off = 1; off < 16; off <<= 1) {
            #pragma unroll
            for (int i = 0; i < 4; i++)
                pm[i] = fmaxf(pm[i], __shfl_xor_sync(0xffffffff, pm[i], off));
        }

        float alpha[4], ps[4];
        #pragma unroll
        for (int i = 0; i < 4; i++) {
            float mnew = fmaxf(m_i[i], pm[i]);
            alpha[i] = __expf(m_i[i] - mnew);
            m_i[i] = mnew;
            ps[i] = 0.f;
            #pragma unroll
            for (int j = 0; j < 4; j++) {
                float p = __expf(acc[i][j] - mnew);
                Ps[(ty * 4 + i) * 64 + tx * 4 + j] = p;
                ps[i] += p;
            }
        }
        #pragma unroll
        for (int off = 1; off < 16; off <<= 1) {
            #pragma unroll
            for (int i = 0; i < 4; i++)
                ps[i] += __shfl_xor_sync(0xffffffff, ps[i], off);
        }
        #pragma unroll
        for (int i = 0; i < 4; i++) {
            l_i[i] = l_i[i] * alpha[i] + ps[i];
            #pragma unroll
            for (int c = 0; c < 4; c++) O[i][c] *= alpha[i];
        }
        __syncthreads();

        #pragma unroll
        for (int jj = 0; jj < 64; jj++) {
            float4 v4 = *reinterpret_cast<const float4*>(&Vs[jj * 64 + tx * 4]);
            float vv[4] = {v4.x, v4.y, v4.z, v4.w};
            float a[4];
            #pragma unroll
            for (int i = 0; i < 4; i++) a[i] = Ps[(ty * 4 + i) * 64 + jj];
            #pragma unroll
            for (int i = 0; i < 4; i++)
                #pragma unroll
                for (int c = 0; c < 4; c++)
                    O[i][c] = fmaf(a[i], vv[c], O[i][c]);
        }
        __syncthreads();
    }

    int h = bh & (HH - 1);
    int b = bh >> 4;
    #pragma unroll
    for (int i = 0; i < 4; i++) {
        int row = mb * 64 + ty * 4 + i;
        float inv = 1.f / l_i[i];
        size_t off = ((size_t)b * TT + row) * CC + h * DD + tx * 4;
        #pragma unroll
        for (int c = 0; c < 4; c++)
            g_y[off + c] = O[i][c] * inv;
    }
    (void)y;
}

// ---------------------------------------------------------------------------
// Launch
// ---------------------------------------------------------------------------
extern "C" void kernel_launch(void* const* d_in, const int* in_sizes, int n_in,
                              void* d_out, int out_size)
{
    const float* x       = (const float*)d_in[0];
    const float* W_share = (const float*)d_in[1];
    const float* b_share = (const float*)d_in[2];
    const float* Wq      = (const float*)d_in[3];
    const float* bq      = (const float*)d_in[4];
    const float* Wk      = (const float*)d_in[5];
    const float* bk      = (const float*)d_in[6];
    const float* Wv      = (const float*)d_in[7];
    const float* bv      = (const float*)d_in[8];
    const float* Wo      = (const float*)d_in[9];
    const float* bo      = (const float*)d_in[10];
    float* out = (float*)d_out;

    float *p_share, *p_qp, *p_kp, *p_vf, *p_y;
    float *p_WqT, *p_WkT, *p_WvT, *p_WoT;
    cudaGetSymbolAddress((void**)&p_share, g_share);
    cudaGetSymbolAddress((void**)&p_qp, g_qp);
    cudaGetSymbolAddress((void**)&p_kp, g_kp);
    cudaGetSymbolAddress((void**)&p_vf, g_vf);
    cudaGetSymbolAddress((void**)&p_y, g_y);
    cudaGetSymbolAddress((void**)&p_WqT, g_WqT);
    cudaGetSymbolAddress((void**)&p_WkT, g_WkT);
    cudaGetSymbolAddress((void**)&p_WvT, g_WvT);
    cudaGetSymbolAddress((void**)&p_WoT, g_WoT);

    dim3 blk(256);
    dim3 tblk(32, 8);

    // Weight transposes (K-major B operand for mma row.col)
    transpose_kernel<<<dim3(768 / 32, 1024 / 32), tblk>>>(Wq, p_WqT, 1024, 768);
    transpose_kernel<<<dim3(768 / 32, 1024 / 32), tblk>>>(Wk, p_WkT, 1024, 768);
    transpose_kernel<<<dim3(1024 / 32, 1024 / 32), tblk>>>(Wv, p_WvT, 1024, 1024);
    transpose_kernel<<<dim3(1024 / 32, 1024 / 32), tblk>>>(Wo, p_WoT, 1024, 1024);

    // Tiny shared projection (SIMT)
    gemm_bias_kernel<<<dim3(1, MM / 64), blk>>>(x, W_share, b_share, p_share,
                                                MM, SHARED_D, CC);

    // Tensor-core projections (mma.sync tf32)
    gemm_tf32mma<<<dim3(6, MM / 128), blk>>>(x, p_WqT, bq, p_qp, 768);
    gemm_tf32mma<<<dim3(6, MM / 128), blk>>>(x, p_WkT, bk, p_kp, 768);
    gemm_tf32mma<<<dim3(8, MM / 128), blk>>>(x, p_WvT, bv, p_vf, 1024);

    // Assemble q/k/v into (BH, T, 64)
    assemble_qkv_kernel<<<(BH * TT * DD) / 256, blk>>>();

    // Flash attention
    cudaFuncSetAttribute(flash_attn_kernel, cudaFuncAttributeMaxDynamicSharedMemorySize, 65536);
    flash_attn_kernel<<<dim3(TT / 64, BH), blk, 65536>>>(p_y);

    // Output projection (tensor core)
    gemm_tf32mma<<<dim3(8, MM / 128), blk>>>(p_y, p_WoT, bo, out, 1024);

    (void)in_sizes; (void)n_in; (void)out_size;
}

// round 8
// speedup vs baseline: 3.8246x; 2.1036x over previous
#include <cuda_runtime.h>
#include <cuda_bf16.h>
#include <cstdint>

// Problem constants
#define BB 4
#define TT 2048
#define CC 1024
#define HH 16
#define DD 64
#define SHARED_D 16
#define PRIV_D 48
#define MM (BB * TT)          // 8192 token rows
#define BH (BB * HH)          // 64 batch-heads
#define GK 1024               // inner K of all projections

// ---------------------------------------------------------------------------
// Scratch (device globals; no allocation allowed)
// ---------------------------------------------------------------------------
__device__ float g_share[MM * SHARED_D];
__device__ float g_qp[MM * (HH * PRIV_D)];
__device__ float g_kp[MM * (HH * PRIV_D)];
__device__ float g_vf[MM * CC];
__device__ float g_q[BH * TT * DD];
__device__ float g_k[BH * TT * DD];
__device__ float g_v[BH * TT * DD];
__device__ float g_y[MM * CC];
// Transposed weights, K-major [N, K]
__device__ float g_WqT[768 * 1024];
__device__ float g_WkT[768 * 1024];
__device__ float g_WvT[1024 * 1024];
__device__ float g_WoT[1024 * 1024];

// ---------------------------------------------------------------------------
// tf32 helpers (mma.sync path — portable PTX)
// ---------------------------------------------------------------------------
static __device__ __forceinline__ uint32_t f2tf32(float x) {
    uint32_t r;
    asm("cvt.rna.tf32.f32 %0, %1;" : "=r"(r) : "f"(x));
    return r;
}

#define MMA_TF32(d, a, b) \
    asm volatile("mma.sync.aligned.m16n8k8.row.col.f32.tf32.tf32.f32 " \
                 "{%0,%1,%2,%3}, {%4,%5,%6,%7}, {%8,%9}, {%0,%1,%2,%3};" \
                 : "+f"((d)[0]), "+f"((d)[1]), "+f"((d)[2]), "+f"((d)[3]) \
                 : "r"((a)[0]), "r"((a)[1]), "r"((a)[2]), "r"((a)[3]), \
                   "r"((b)[0]), "r"((b)[1]))

// ---------------------------------------------------------------------------
// Weight transpose: W [K,N] row-major -> Wt [N,K] row-major
// ---------------------------------------------------------------------------
__global__ void transpose_kernel(const float* __restrict__ W, float* __restrict__ Wt,
                                 int K, int N) {
    __shared__ float tile[32][33];
    int n0 = blockIdx.x * 32, k0 = blockIdx.y * 32;
    int tx = threadIdx.x, ty = threadIdx.y;
    #pragma unroll
    for (int i = 0; i < 4; i++)
        tile[ty + i * 8][tx] = W[(size_t)(k0 + ty + i * 8) * N + n0 + tx];
    __syncthreads();
    #pragma unroll
    for (int i = 0; i < 4; i++)
        Wt[(size_t)(n0 + ty + i * 8) * K + k0 + tx] = tile[tx][ty + i * 8];
}

// ---------------------------------------------------------------------------
// Tensor-core GEMM (mma.sync tf32): C[M,N] = A[M,1024] @ Bt[N,1024]^T + bias[N]
// ---------------------------------------------------------------------------
#define SMS 36  // smem row stride (floats)

__global__ __launch_bounds__(256) void gemm_tf32mma(const float* __restrict__ A,
                                                    const float* __restrict__ Bt,
                                                    const float* __restrict__ bias,
                                                    float* __restrict__ C, int N)
{
    __shared__ uint32_t As[128 * SMS];
    __shared__ uint32_t Bs[128 * SMS];

    const int tid = threadIdx.x;
    const int wid = tid >> 5, lane = tid & 31;
    const int wm = wid & 1, wn = wid >> 1;
    const int g = lane >> 2, t = lane & 3;
    const int m0 = blockIdx.y * 128, n0 = blockIdx.x * 128;

    float acc[4][4][4] = {};
    float4 ra[4], rb[4];

    #pragma unroll
    for (int l = 0; l < 4; l++) {
        int idx = tid + l * 256;
        int row = idx >> 3, c4 = idx & 7;
        ra[l] = *(const float4*)(A  + (size_t)(m0 + row) * GK + c4 * 4);
        rb[l] = *(const float4*)(Bt + (size_t)(n0 + row) * GK + c4 * 4);
    }

    for (int kc = 0; kc < 32; kc++) {
        __syncthreads();
        #pragma unroll
        for (int l = 0; l < 4; l++) {
            int idx = tid + l * 256;
            int row = idx >> 3, c4 = idx & 7;
            uint4 ua, ub;
            ua.x = f2tf32(ra[l].x); ua.y = f2tf32(ra[l].y);
            ua.z = f2tf32(ra[l].z); ua.w = f2tf32(ra[l].w);
            ub.x = f2tf32(rb[l].x); ub.y = f2tf32(rb[l].y);
            ub.z = f2tf32(rb[l].z); ub.w = f2tf32(rb[l].w);
            *(uint4*)&As[row * SMS + c4 * 4] = ua;
            *(uint4*)&Bs[row * SMS + c4 * 4] = ub;
        }
        __syncthreads();

        if (kc + 1 < 32) {
            #pragma unroll
            for (int l = 0; l < 4; l++) {
                int idx = tid + l * 256;
                int row = idx >> 3, c4 = idx & 7;
                ra[l] = *(const float4*)(A  + (size_t)(m0 + row) * GK + (kc + 1) * 32 + c4 * 4);
                rb[l] = *(const float4*)(Bt + (size_t)(n0 + row) * GK + (kc + 1) * 32 + c4 * 4);
            }
        }

        #pragma unroll
        for (int ks = 0; ks < 4; ks++) {
            uint32_t af[4][4], bf[4][2];
            #pragma unroll
            for (int mt = 0; mt < 4; mt++) {
                int r = wm * 64 + mt * 16 + g;
                int c = ks * 8 + t;
                af[mt][0] = As[r * SMS + c];
                af[mt][1] = As[(r + 8) * SMS + c];
                af[mt][2] = As[r * SMS + c + 4];
                af[mt][3] = As[(r + 8) * SMS + c + 4];
            }
            #pragma unroll
            for (int nt = 0; nt < 4; nt++) {
                int n = wn * 32 + nt * 8 + g;
                int c = ks * 8 + t;
                bf[nt][0] = Bs[n * SMS + c];
                bf[nt][1] = Bs[n * SMS + c + 4];
            }
            #pragma unroll
            for (int mt = 0; mt < 4; mt++)
                #pragma unroll
                for (int nt = 0; nt < 4; nt++)
                    MMA_TF32(acc[mt][nt], af[mt], bf[nt]);
        }
    }

    #pragma unroll
    for (int mt = 0; mt < 4; mt++) {
        int r0 = m0 + wm * 64 + mt * 16 + g;
        #pragma unroll
        for (int nt = 0; nt < 4; nt++) {
            int cc = n0 + wn * 32 + nt * 8 + 2 * t;
            float2 bi = *(const float2*)(bias + cc);
            float2 o0 = { acc[mt][nt][0] + bi.x, acc[mt][nt][1] + bi.y };
            float2 o1 = { acc[mt][nt][2] + bi.x, acc[mt][nt][3] + bi.y };
            *(float2*)(C + (size_t)r0 * N + cc) = o0;
            *(float2*)(C + (size_t)(r0 + 8) * N + cc) = o1;
        }
    }
}

// ---------------------------------------------------------------------------
// SIMT GEMM (tiny N=16 shared projection)
// ---------------------------------------------------------------------------
__global__ void gemm_bias_kernel(const float* __restrict__ A,
                                 const float* __restrict__ W,
                                 const float* __restrict__ bias,
                                 float* __restrict__ C,
                                 int M, int N, int K)
{
    const int TM = 64, TN = 64, TK = 16;
    __shared__ float Asm[TK][TM];
    __shared__ float Wsm[TK][TN];

    int tid = threadIdx.x;
    int tx = tid & 15;
    int ty = tid >> 4;
    int m0 = blockIdx.y * TM;
    int n0 = blockIdx.x * TN;

    float acc[4][4] = {};

    for (int k0 = 0; k0 < K; k0 += TK) {
        #pragma unroll
        for (int l = 0; l < 4; l++) {
            int idx = tid + l * 256;
            int mi = idx >> 4;
            int ki = idx & 15;
            Asm[ki][mi] = A[(size_t)(m0 + mi) * K + (k0 + ki)];
        }
        #pragma unroll
        for (int l = 0; l < 4; l++) {
            int idx = tid + l * 256;
            int ki = idx >> 6;
            int ni = idx & 63;
            int gn = n0 + ni;
            Wsm[ki][ni] = (gn < N) ? W[(size_t)(k0 + ki) * N + gn] : 0.f;
        }
        __syncthreads();

        #pragma unroll
        for (int kk = 0; kk < TK; kk++) {
            float4 a4 = *reinterpret_cast<const float4*>(&Asm[kk][ty * 4]);
            float4 w4 = *reinterpret_cast<const float4*>(&Wsm[kk][tx * 4]);
            float a[4] = {a4.x, a4.y, a4.z, a4.w};
            float w[4] = {w4.x, w4.y, w4.z, w4.w};
            #pragma unroll
            for (int i = 0; i < 4; i++)
                #pragma unroll
                for (int j = 0; j < 4; j++)
                    acc[i][j] = fmaf(a[i], w[j], acc[i][j]);
        }
        __syncthreads();
    }

    #pragma unroll
    for (int i = 0; i < 4; i++) {
        int gm = m0 + ty * 4 + i;
        #pragma unroll
        for (int j = 0; j < 4; j++) {
            int gn = n0 + tx * 4 + j;
            if (gn < N)
                C[(size_t)gm * N + gn] = acc[i][j] + bias[gn];
        }
    }
}

// ---------------------------------------------------------------------------
// Assemble q/k/v into (B*H, T, 64) layout.
// ---------------------------------------------------------------------------
__global__ void assemble_qkv_kernel()
{
    int idx = blockIdx.x * blockDim.x + threadIdx.x;
    int d = idx & 63;
    int t = (idx >> 6) & (TT - 1);
    int h = (idx >> 17) & (HH - 1);
    int b = idx >> 21;
    size_t row = (size_t)b * TT + t;

    float qv, kv;
    if (d < SHARED_D) {
        float s = g_share[row * SHARED_D + d];
        qv = s; kv = s;
    } else {
        size_t p = row * (HH * PRIV_D) + h * PRIV_D + (d - SHARED_D);
        qv = g_qp[p];
        kv = g_kp[p];
    }
    g_q[idx] = qv;
    g_k[idx] = kv;
    g_v[idx] = g_vf[row * CC + h * DD + d];
}

// ---------------------------------------------------------------------------
// Flash attention with mma.sync tf32.
// CTA: 128 q-rows x 64 kv-cols per iteration. 8 warps, 16 rows each.
// grid = (T/128, B*H), block = 256.
// ---------------------------------------------------------------------------
#define FAS 68   // smem row stride (u32 elements)

__global__ __launch_bounds__(256) void flash_attn_mma()
{
    extern __shared__ uint32_t fsm[];
    uint32_t* Qs  = fsm;                    // 128*68
    uint32_t* Ks  = Qs + 128 * FAS;         // 64*68
    uint32_t* Vts = Ks + 64 * FAS;          // 64*68  (d-major: Vts[d][j])
    uint32_t* Ps  = Vts + 64 * FAS;         // 128*68

    const int mb  = blockIdx.x;
    const int bh  = blockIdx.y;
    const int tid = threadIdx.x;
    const int w   = tid >> 5, lane = tid & 31;
    const int g   = lane >> 2, t = lane & 3;
    const size_t base = (size_t)bh * TT * DD;
    const float scale = 0.125f;

    // Load Q tile [128, 64] as tf32
    #pragma unroll
    for (int l = 0; l < 8; l++) {
        int idx = tid + l * 256;             // float4 slots
        int i = idx >> 4, d4 = idx & 15;
        float4 v = *(const float4*)(g_q + base + (size_t)(mb * 128 + i) * DD + d4 * 4);
        uint32_t* p = &Qs[i * FAS + d4 * 4];
        p[0] = f2tf32(v.x); p[1] = f2tf32(v.y); p[2] = f2tf32(v.z); p[3] = f2tf32(v.w);
    }

    const int r0 = w * 16 + g;               // local row (and r0+8)
    const int gr0 = mb * 128 + r0;
    const int gr1 = gr0 + 8;
    const int wrow_max = mb * 128 + w * 16 + 15;

    float m0s = -1e30f, m1s = -1e30f, l0s = 0.f, l1s = 0.f;
    float acc_o[8][4] = {};

    const int jb_max = 2 * mb + 1;
    for (int jb = 0; jb <= jb_max; jb++) {
        __syncthreads();
        // Load K row-major tf32, V transposed (d-major) tf32
        #pragma unroll
        for (int l = 0; l < 4; l++) {
            int idx = tid + l * 256;
            int j = idx >> 4, d4 = idx & 15;
            size_t gaddr = base + (size_t)(jb * 64 + j) * DD + d4 * 4;
            float4 kv = *(const float4*)(g_k + gaddr);
            float4 vv = *(const float4*)(g_v + gaddr);
            uint32_t* kp = &Ks[j * FAS + d4 * 4];
            kp[0] = f2tf32(kv.x); kp[1] = f2tf32(kv.y);
            kp[2] = f2tf32(kv.z); kp[3] = f2tf32(kv.w);
            Vts[(d4 * 4 + 0) * FAS + j] = f2tf32(vv.x);
            Vts[(d4 * 4 + 1) * FAS + j] = f2tf32(vv.y);
            Vts[(d4 * 4 + 2) * FAS + j] = f2tf32(vv.z);
            Vts[(d4 * 4 + 3) * FAS + j] = f2tf32(vv.w);
        }
        __syncthreads();

        if (jb * 64 > wrow_max) continue;    // block fully above this warp's rows

        // S = Q @ K^T  (warp: 16 rows x 64 cols)
        float s[8][4] = {};
        #pragma unroll
        for (int ks = 0; ks < 8; ks++) {
            uint32_t a[4];
            a[0] = Qs[r0 * FAS + ks * 8 + t];
            a[1] = Qs[(r0 + 8) * FAS + ks * 8 + t];
            a[2] = Qs[r0 * FAS + ks * 8 + t + 4];
            a[3] = Qs[(r0 + 8) * FAS + ks * 8 + t + 4];
            #pragma unroll
            for (int nt = 0; nt < 8; nt++) {
                uint32_t b[2];
                b[0] = Ks[(nt * 8 + g) * FAS + ks * 8 + t];
                b[1] = Ks[(nt * 8 + g) * FAS + ks * 8 + t + 4];
                MMA_TF32(s[nt], a, b);
            }
        }

        // scale + causal mask
        #pragma unroll
        for (int nt = 0; nt < 8; nt++) {
            int c0 = jb * 64 + nt * 8 + 2 * t;
            s[nt][0] = (c0     <= gr0) ? s[nt][0] * scale : -1e30f;
            s[nt][1] = (c0 + 1 <= gr0) ? s[nt][1] * scale : -1e30f;
            s[nt][2] = (c0     <= gr1) ? s[nt][2] * scale : -1e30f;
            s[nt][3] = (c0 + 1 <= gr1) ? s[nt][3] * scale : -1e30f;
        }

        // row max (local + 4-lane shuffle over t-group)
        float mx0 = -1e30f, mx1 = -1e30f;
        #pragma unroll
        for (int nt = 0; nt < 8; nt++) {
            mx0 = fmaxf(mx0, fmaxf(s[nt][0], s[nt][1]));
            mx1 = fmaxf(mx1, fmaxf(s[nt][2], s[nt][3]));
        }
        mx0 = fmaxf(mx0, __shfl_xor_sync(0xffffffff, mx0, 1));
        mx0 = fmaxf(mx0, __shfl_xor_sync(0xffffffff, mx0, 2));
        mx1 = fmaxf(mx1, __shfl_xor_sync(0xffffffff, mx1, 1));
        mx1 = fmaxf(mx1, __shfl_xor_sync(0xffffffff, mx1, 2));

        float mn0 = fmaxf(m0s, mx0), mn1 = fmaxf(m1s, mx1);
        float al0 = __expf(m0s - mn0), al1 = __expf(m1s - mn1);
        m0s = mn0; m1s = mn1;

        float sum0 = 0.f, sum1 = 0.f;
        #pragma unroll
        for (int nt = 0; nt < 8; nt++) {
            float p0 = __expf(s[nt][0] - mn0);
            float p1 = __expf(s[nt][1] - mn0);
            float p2 = __expf(s[nt][2] - mn1);
            float p3 = __expf(s[nt][3] - mn1);
            sum0 += p0 + p1; sum1 += p2 + p3;
            uint2 w0 = { f2tf32(p0), f2tf32(p1) };
            uint2 w1 = { f2tf32(p2), f2tf32(p3) };
            *(uint2*)&Ps[r0 * FAS + nt * 8 + 2 * t] = w0;
            *(uint2*)&Ps[(r0 + 8) * FAS + nt * 8 + 2 * t] = w1;
        }
        sum0 += __shfl_xor_sync(0xffffffff, sum0, 1);
        sum0 += __shfl_xor_sync(0xffffffff, sum0, 2);
        sum1 += __shfl_xor_sync(0xffffffff, sum1, 1);
        sum1 += __shfl_xor_sync(0xffffffff, sum1, 2);
        l0s = l0s * al0 + sum0;
        l1s = l1s * al1 + sum1;

        #pragma unroll
        for (int nt = 0; nt < 8; nt++) {
            acc_o[nt][0] *= al0; acc_o[nt][1] *= al0;
            acc_o[nt][2] *= al1; acc_o[nt][3] *= al1;
        }
        __syncwarp();

        // O += P @ V   (k-dim = 64 kv cols of this block)
        #pragma unroll
        for (int ks = 0; ks < 8; ks++) {
            uint32_t a[4];
            a[0] = Ps[r0 * FAS + ks * 8 + t];
            a[1] = Ps[(r0 + 8) * FAS + ks * 8 + t];
            a[2] = Ps[r0 * FAS + ks * 8 + t + 4];
            a[3] = Ps[(r0 + 8) * FAS + ks * 8 + t + 4];
            #pragma unroll
            for (int nt = 0; nt < 8; nt++) {
                uint32_t b[2];
                b[0] = Vts[(nt * 8 + g) * FAS + ks * 8 + t];
                b[1] = Vts[(nt * 8 + g) * FAS + ks * 8 + t + 4];
                MMA_TF32(acc_o[nt], a, b);
            }
        }
        __syncwarp();   // done reading Ps before next-iter overwrite
    }

    // Epilogue: y[b, row, h*64 + d]
    const int h = bh & (HH - 1);
    const int b = bh >> 4;
    const float inv0 = 1.f / l0s, inv1 = 1.f / l1s;
    size_t row0 = (size_t)b * TT + mb * 128 + r0;
    #pragma unroll
    for (int nt = 0; nt < 8; nt++) {
        int col = h * DD + nt * 8 + 2 * t;
        float2 o0 = { acc_o[nt][0] * inv0, acc_o[nt][1] * inv0 };
        float2 o1 = { acc_o[nt][2] * inv1, acc_o[nt][3] * inv1 };
        *(float2*)(g_y + row0 * CC + col) = o0;
        *(float2*)(g_y + (row0 + 8) * CC + col) = o1;
    }
}

// ---------------------------------------------------------------------------
// Launch
// ---------------------------------------------------------------------------
extern "C" void kernel_launch(void* const* d_in, const int* in_sizes, int n_in,
                              void* d_out, int out_size)
{
    const float* x       = (const float*)d_in[0];
    const float* W_share = (const float*)d_in[1];
    const float* b_share = (const float*)d_in[2];
    const float* Wq      = (const float*)d_in[3];
    const float* bq      = (const float*)d_in[4];
    const float* Wk      = (const float*)d_in[5];
    const float* bk      = (const float*)d_in[6];
    const float* Wv      = (const float*)d_in[7];
    const float* bv      = (const float*)d_in[8];
    const float* Wo      = (const float*)d_in[9];
    const float* bo      = (const float*)d_in[10];
    float* out = (float*)d_out;

    float *p_share, *p_qp, *p_kp, *p_vf, *p_y;
    float *p_WqT, *p_WkT, *p_WvT, *p_WoT;
    cudaGetSymbolAddress((void**)&p_share, g_share);
    cudaGetSymbolAddress((void**)&p_qp, g_qp);
    cudaGetSymbolAddress((void**)&p_kp, g_kp);
    cudaGetSymbolAddress((void**)&p_vf, g_vf);
    cudaGetSymbolAddress((void**)&p_y, g_y);
    cudaGetSymbolAddress((void**)&p_WqT, g_WqT);
    cudaGetSymbolAddress((void**)&p_WkT, g_WkT);
    cudaGetSymbolAddress((void**)&p_WvT, g_WvT);
    cudaGetSymbolAddress((void**)&p_WoT, g_WoT);

    dim3 blk(256);
    dim3 tblk(32, 8);

    // Weight transposes (K-major B operand for mma row.col)
    transpose_kernel<<<dim3(768 / 32, 1024 / 32), tblk>>>(Wq, p_WqT, 1024, 768);
    transpose_kernel<<<dim3(768 / 32, 1024 / 32), tblk>>>(Wk, p_WkT, 1024, 768);
    transpose_kernel<<<dim3(1024 / 32, 1024 / 32), tblk>>>(Wv, p_WvT, 1024, 1024);
    transpose_kernel<<<dim3(1024 / 32, 1024 / 32), tblk>>>(Wo, p_WoT, 1024, 1024);

    // Tiny shared projection (SIMT)
    gemm_bias_kernel<<<dim3(1, MM / 64), blk>>>(x, W_share, b_share, p_share,
                                                MM, SHARED_D, CC);

    // Tensor-core projections (mma.sync tf32)
    gemm_tf32mma<<<dim3(6, MM / 128), blk>>>(x, p_WqT, bq, p_qp, 768);
    gemm_tf32mma<<<dim3(6, MM / 128), blk>>>(x, p_WkT, bk, p_kp, 768);
    gemm_tf32mma<<<dim3(8, MM / 128), blk>>>(x, p_WvT, bv, p_vf, 1024);

    // Assemble q/k/v into (BH, T, 64)
    assemble_qkv_kernel<<<(BH * TT * DD) / 256, blk>>>();

    // Flash attention (tensor core)
    const int FA_SMEM = (128 * FAS + 64 * FAS + 64 * FAS + 128 * FAS) * 4;  // 104448
    cudaFuncSetAttribute(flash_attn_mma, cudaFuncAttributeMaxDynamicSharedMemorySize, FA_SMEM);
    flash_attn_mma<<<dim3(TT / 128, BH), blk, FA_SMEM>>>();

    // Output projection (tensor core)
    gemm_tf32mma<<<dim3(8, MM / 128), blk>>>(p_y, p_WoT, bo, out, 1024);

    (void)in_sizes; (void)n_in; (void)out_size;
}